// round 4
// baseline (speedup 1.0000x reference)
#include <cuda_runtime.h>
#include <cuda_fp16.h>

// QConv2d: 3x3 conv, B=16, C=32, N=64, H=W=56, stride 1, pad 1.
// Bit-exact emulation of per-k fp16 (E5M10) requantized accumulation:
//   p   = fp16(fp32(a * w))  -> FMUL.rn + cvt.rn.f16x2.f32 (packs the 2 n-lanes)
//   acc = fp16(acc + p)      -> HADD2 (== fp16(fp32 add), innocuous dbl rounding)
// k order = c*9 + i*3 + j, matching lax.scan order in the reference.
//
// R4: back to scalar FMUL (f32x2 proved half-rate + chain-lengthening).
// TB=896 (2 px/thread) -> 2 CTAs/SM = 56 warps/SM for issue-latency hiding.

#define TB 896

#define ROWP 60                           // padded input row (floats)
#define SIN_FLOATS (32 * 3 * ROWP)        // 5760
#define SW_FLOATS  (288 * 64)             // 18432
#define SMEM_BYTES ((SIN_FLOATS + SW_FLOATS) * 4)   // 96768 -> 2 CTAs/SM

__device__ __forceinline__ __half2 cvt_pair(float n0, float n1) {
    unsigned h;
    // cvt.rn.f16x2.f32 d, a, b : a -> upper half, b -> lower half
    asm("cvt.rn.f16x2.f32 %0, %1, %2;" : "=r"(h) : "f"(n1), "f"(n0));
    return *reinterpret_cast<__half2*>(&h);
}

__global__ void __launch_bounds__(TB, 2) qconv2d_kernel(
    const float* __restrict__ x,      // [16][32][56][56]
    const float* __restrict__ w,      // [64][32][3][3] = [64][288]
    const float* __restrict__ bias,   // [64]
    float* __restrict__ out)          // [16][64][56][56]
{
    extern __shared__ float sm[];
    float* sin = sm;                      // [c][r(3)][ROWP]
    float* sw  = sm + SIN_FLOATS;         // [k=288][n=64], fp16-valued fp32

    const int y0  = blockIdx.x;   // output row 0..55
    const int b   = blockIdx.y;   // batch 0..15
    const int tid = threadIdx.x;

    // ---- weights: coalesced gmem read, transpose to [k][n], quantize ----
    for (int idx = tid; idx < 64 * 288; idx += TB) {
        int n = idx / 288;
        int k = idx % 288;
        sw[k * 64 + n] = __half2float(__float2half_rn(w[idx]));
    }

    // ---- input rows y0-1..y0+1, 32 ch, padded row of 60 (x offset by 1) ----
    const float* xb = x + (size_t)b * 32 * 56 * 56;
    for (int idx = tid; idx < SIN_FLOATS; idx += TB) {
        int c   = idx / (3 * ROWP);
        int r3  = idx % (3 * ROWP);
        int r   = r3 / ROWP;
        int xs  = r3 % ROWP;
        int yg  = y0 - 1 + r;
        int xg  = xs - 1;
        float v = 0.0f;
        if (yg >= 0 && yg < 56 && xg >= 0 && xg < 56)
            v = xb[(c * 56 + yg) * 56 + xg];
        sin[idx] = v;
    }
    __syncthreads();

    const int tn = tid & 31;      // n-pair: n0 = 2*tn, n1 = 2*tn+1  (lane id)
    const int g  = tid >> 5;      // pixel group 0..27 (uniform across warp)
    const int x0 = g * 2;         // output x base, 2 px per thread

    __half2 acc0 = __float2half2_rn(0.0f);   // px x0
    __half2 acc1 = acc0;                     // px x0+1

    const float* swt = sw + 2 * tn;
    const float* ab  = sin + x0;  // 8B aligned

    #pragma unroll 1
    for (int c = 0; c < 32; ++c) {
        #pragma unroll
        for (int i = 0; i < 3; ++i) {
            const float* ar = ab + (c * 3 + i) * ROWP;
            // a0..a3 : input xs = x0 .. x0+3 (broadcast LDS.64 x2)
            float2 a01 = *reinterpret_cast<const float2*>(ar);
            float2 a23 = *reinterpret_cast<const float2*>(ar + 2);

            const float* wr = swt + (c * 9 + i * 3) * 64;
            float2 w0 = *reinterpret_cast<const float2*>(wr);
            float2 w1 = *reinterpret_cast<const float2*>(wr + 64);
            float2 w2 = *reinterpret_cast<const float2*>(wr + 128);

            // j = 0: px0 uses a0, px1 uses a1
            acc0 = __hadd2(acc0, cvt_pair(a01.x * w0.x, a01.x * w0.y));
            acc1 = __hadd2(acc1, cvt_pair(a01.y * w0.x, a01.y * w0.y));
            // j = 1: px0 uses a1, px1 uses a2
            acc0 = __hadd2(acc0, cvt_pair(a01.y * w1.x, a01.y * w1.y));
            acc1 = __hadd2(acc1, cvt_pair(a23.x * w1.x, a23.x * w1.y));
            // j = 2: px0 uses a2, px1 uses a3
            acc0 = __hadd2(acc0, cvt_pair(a23.x * w2.x, a23.x * w2.y));
            acc1 = __hadd2(acc1, cvt_pair(a23.y * w2.x, a23.y * w2.y));
        }
    }

    // ---- epilogue: out = fp32(fp16(acc + fp16(bias))) ----
    const int n0 = 2 * tn;
    __half2 qb = __halves2half2(__float2half_rn(bias[n0]),
                                __float2half_rn(bias[n0 + 1]));

    __half2 r0 = __hadd2(acc0, qb);   // px0: (n0, n1)
    __half2 r1 = __hadd2(acc1, qb);   // px1: (n0, n1)

    float2 v0, v1;
    v0.x = __low2float(r0);  v0.y = __low2float(r1);   // n0: px0, px1
    v1.x = __high2float(r0); v1.y = __high2float(r1);  // n1: px0, px1

    size_t o0 = (((size_t)b * 64 + n0) * 56 + y0) * 56 + x0;
    size_t o1 = (((size_t)b * 64 + n0 + 1) * 56 + y0) * 56 + x0;
    *reinterpret_cast<float2*>(out + o0) = v0;
    *reinterpret_cast<float2*>(out + o1) = v1;
}

extern "C" void kernel_launch(void* const* d_in, const int* in_sizes, int n_in,
                              void* d_out, int out_size)
{
    const float* x    = (const float*)d_in[0];
    const float* w    = (const float*)d_in[1];
    const float* bias = (const float*)d_in[2];
    float* out = (float*)d_out;

    cudaFuncSetAttribute(qconv2d_kernel,
                         cudaFuncAttributeMaxDynamicSharedMemorySize,
                         SMEM_BYTES);

    dim3 grid(56, 16);   // (output row, batch)
    qconv2d_kernel<<<grid, TB, SMEM_BYTES>>>(x, w, bias, out);
}

// round 5
// speedup vs baseline: 1.3685x; 1.3685x over previous
#include <cuda_runtime.h>
#include <cuda_fp16.h>

// QConv2d: 3x3 conv, B=16, C=32, N=64, H=W=56, stride 1, pad 1.
// Bit-exact emulation of per-k fp16 (E5M10) requantized accumulation:
//   p   = fp16(fp32(a * w))  -> FMUL.rn + cvt.rn.f16x2.f32 (packs 2 n-lanes)
//   acc = fp16(acc + p)      -> HADD2 (== fp16(fp32 add), innocuous dbl rounding)
// k order = c*9 + i*3 + j, matching lax.scan order in the reference.
//
// R5: channel-split blocks (32 of 64 n per block) -> smem 67.6KB -> 3 CTAs/SM
// (42 warps). Warp = 16 n-pairs x 2 px-half-groups, so weight LDS.64 spans
// 128B (1 wavefront, upper half-warp broadcasts). Block covers 2 output rows.

#define TB 448

#define ROWP 60                            // padded input row (floats)
#define SIN_FLOATS (32 * 4 * ROWP)         // 7680  : 32 ch x 4 rows (2 + halo)
#define SW_FLOATS  (288 * 32)              // 9216  : [k][n-half]
#define SMEM_BYTES ((SIN_FLOATS + SW_FLOATS) * 4)   // 67584 -> 3 CTAs/SM

__device__ __forceinline__ __half2 cvt_pair(float n0, float n1) {
    unsigned h;
    // cvt.rn.f16x2.f32 d, a, b : a -> upper half, b -> lower half
    asm("cvt.rn.f16x2.f32 %0, %1, %2;" : "=r"(h) : "f"(n1), "f"(n0));
    return *reinterpret_cast<__half2*>(&h);
}

__global__ void __launch_bounds__(TB, 3) qconv2d_kernel(
    const float* __restrict__ x,      // [16][32][56][56]
    const float* __restrict__ w,      // [64][32][3][3] = [64][288]
    const float* __restrict__ bias,   // [64]
    float* __restrict__ out)          // [16][64][56][56]
{
    extern __shared__ float sm[];
    float* sin = sm;                      // [c][r(4)][ROWP]
    float* sw  = sm + SIN_FLOATS;         // [k=288][nc=32], fp16-valued fp32

    const int yp    = blockIdx.x;     // row pair 0..27 -> rows 2*yp, 2*yp+1
    const int b     = blockIdx.y;     // batch 0..15
    const int nhalf = blockIdx.z;     // 0: n 0..31, 1: n 32..63
    const int tid   = threadIdx.x;
    const int y0    = 2 * yp;

    // ---- weights for this n-half: coalesced read, transpose to [k][nc] ----
    for (int idx = tid; idx < 32 * 288; idx += TB) {
        int nc = idx / 288;
        int k  = idx % 288;
        sw[k * 32 + nc] = __half2float(__float2half_rn(w[(nhalf * 32 + nc) * 288 + k]));
    }

    // ---- input rows y0-1..y0+2, 32 ch, padded rows of 60 (x offset by 1) ----
    const float* xb = x + (size_t)b * 32 * 56 * 56;
    for (int idx = tid; idx < SIN_FLOATS; idx += TB) {
        int c   = idx / (4 * ROWP);
        int r4  = idx % (4 * ROWP);
        int r   = r4 / ROWP;
        int xs  = r4 % ROWP;
        int yg  = y0 - 1 + r;
        int xg  = xs - 1;
        float v = 0.0f;
        if (yg >= 0 && yg < 56 && xg >= 0 && xg < 56)
            v = xb[(c * 56 + yg) * 56 + xg];
        sin[idx] = v;
    }
    __syncthreads();

    const int lane = tid & 31;
    const int wrp  = tid >> 5;        // 0..13
    const int np   = lane & 15;       // n-pair within half: channels 2np, 2np+1
    const int h    = lane >> 4;       // px half-group 0/1
    const int rowsel = wrp / 7;       // 0: row y0, 1: row y0+1
    const int x0   = (wrp % 7) * 8 + h * 4;   // output x base (4 px)

    __half2 acc0 = __float2half2_rn(0.0f);
    __half2 acc1 = acc0, acc2 = acc0, acc3 = acc0;

    const float* swt = sw + 2 * np;
    const float* ab  = sin + rowsel * ROWP + x0;   // 16B aligned (x0 % 4 == 0)

    #pragma unroll 2
    for (int c = 0; c < 32; ++c) {
        #pragma unroll
        for (int i = 0; i < 3; ++i) {
            const float* ar = ab + (c * 4 + i) * ROWP;
            float4 a03 = *reinterpret_cast<const float4*>(ar);       // xs x0..x0+3
            float2 a45 = *reinterpret_cast<const float2*>(ar + 4);   // xs x0+4,5

            const float* wr = swt + (c * 9 + i * 3) * 32;
            float2 w0 = *reinterpret_cast<const float2*>(wr);        // j=0
            float2 w1 = *reinterpret_cast<const float2*>(wr + 32);   // j=1
            float2 w2 = *reinterpret_cast<const float2*>(wr + 64);   // j=2

            // j = 0
            acc0 = __hadd2(acc0, cvt_pair(a03.x * w0.x, a03.x * w0.y));
            acc1 = __hadd2(acc1, cvt_pair(a03.y * w0.x, a03.y * w0.y));
            acc2 = __hadd2(acc2, cvt_pair(a03.z * w0.x, a03.z * w0.y));
            acc3 = __hadd2(acc3, cvt_pair(a03.w * w0.x, a03.w * w0.y));
            // j = 1
            acc0 = __hadd2(acc0, cvt_pair(a03.y * w1.x, a03.y * w1.y));
            acc1 = __hadd2(acc1, cvt_pair(a03.z * w1.x, a03.z * w1.y));
            acc2 = __hadd2(acc2, cvt_pair(a03.w * w1.x, a03.w * w1.y));
            acc3 = __hadd2(acc3, cvt_pair(a45.x * w1.x, a45.x * w1.y));
            // j = 2
            acc0 = __hadd2(acc0, cvt_pair(a03.z * w2.x, a03.z * w2.y));
            acc1 = __hadd2(acc1, cvt_pair(a03.w * w2.x, a03.w * w2.y));
            acc2 = __hadd2(acc2, cvt_pair(a45.x * w2.x, a45.x * w2.y));
            acc3 = __hadd2(acc3, cvt_pair(a45.y * w2.x, a45.y * w2.y));
        }
    }

    // ---- epilogue: out = fp32(fp16(acc + fp16(bias))) ----
    const int n0 = nhalf * 32 + 2 * np;
    __half2 qb = __halves2half2(__float2half_rn(bias[n0]),
                                __float2half_rn(bias[n0 + 1]));

    __half2 r0 = __hadd2(acc0, qb);
    __half2 r1 = __hadd2(acc1, qb);
    __half2 r2 = __hadd2(acc2, qb);
    __half2 r3 = __hadd2(acc3, qb);

    float4 v0, v1;
    v0.x = __low2float(r0);  v0.y = __low2float(r1);
    v0.z = __low2float(r2);  v0.w = __low2float(r3);
    v1.x = __high2float(r0); v1.y = __high2float(r1);
    v1.z = __high2float(r2); v1.w = __high2float(r3);

    const int y = y0 + rowsel;
    size_t o0 = (((size_t)b * 64 + n0) * 56 + y) * 56 + x0;
    size_t o1 = (((size_t)b * 64 + n0 + 1) * 56 + y) * 56 + x0;
    *reinterpret_cast<float4*>(out + o0) = v0;
    *reinterpret_cast<float4*>(out + o1) = v1;
}

extern "C" void kernel_launch(void* const* d_in, const int* in_sizes, int n_in,
                              void* d_out, int out_size)
{
    const float* x    = (const float*)d_in[0];
    const float* w    = (const float*)d_in[1];
    const float* bias = (const float*)d_in[2];
    float* out = (float*)d_out;

    cudaFuncSetAttribute(qconv2d_kernel,
                         cudaFuncAttributeMaxDynamicSharedMemorySize,
                         SMEM_BYTES);

    dim3 grid(28, 16, 2);   // (row pair, batch, n-half)
    qconv2d_kernel<<<grid, TB, SMEM_BYTES>>>(x, w, bias, out);
}

// round 6
// speedup vs baseline: 1.6192x; 1.1832x over previous
#include <cuda_runtime.h>
#include <cuda_fp16.h>

// QConv2d: 3x3 conv, B=16, C=32, N=64, H=W=56, stride 1, pad 1.
// Per-k fp16 (E5M10) requantized accumulation:
//   p   = fp16(fp32(a * w))  -> FMUL.rn + cvt.rn.f16x2.f32 (packs 2 n-lanes)
//   acc = fp16(acc + p)      -> HADD2
// k order = c*9 + i*3 + j, matching lax.scan order in the reference.
//
// R6: 8 px/thread (amortize weight loads 2x vs R1), channel-split blocks
// (32 of 64 n) -> smem 82944B -> 2 CTAs/SM, 28 warps. Warp = 16 n-pairs x
// 2 px-groups so weight LDS.64 spans 128B (1 wavefront). Block = 4 rows.

#define TB 448

#define ROWP 60                            // padded input row (floats)
#define NROWS 6                            // 4 output rows + halo
#define SIN_FLOATS (32 * NROWS * ROWP)     // 11520
#define SW_FLOATS  (288 * 32)              // 9216
#define SMEM_BYTES ((SIN_FLOATS + SW_FLOATS) * 4)   // 82944 -> 2 CTAs/SM

__device__ __forceinline__ __half2 cvt_pair(float n0, float n1) {
    unsigned h;
    // cvt.rn.f16x2.f32 d, a, b : a -> upper half, b -> lower half
    asm("cvt.rn.f16x2.f32 %0, %1, %2;" : "=r"(h) : "f"(n1), "f"(n0));
    return *reinterpret_cast<__half2*>(&h);
}

__global__ void __launch_bounds__(TB, 2) qconv2d_kernel(
    const float* __restrict__ x,      // [16][32][56][56]
    const float* __restrict__ w,      // [64][32][3][3] = [64][288]
    const float* __restrict__ bias,   // [64]
    float* __restrict__ out)          // [16][64][56][56]
{
    extern __shared__ float sm[];
    float* sin = sm;                      // [c][r(6)][ROWP]
    float* sw  = sm + SIN_FLOATS;         // [k=288][nc=32], fp16-valued fp32

    const int yq    = blockIdx.x;     // row quad 0..13 -> rows 4*yq .. 4*yq+3
    const int b     = blockIdx.y;     // batch 0..15
    const int nhalf = blockIdx.z;     // 0: n 0..31, 1: n 32..63
    const int tid   = threadIdx.x;
    const int y0    = 4 * yq;

    // ---- weights for this n-half: coalesced read, transpose to [k][nc] ----
    for (int idx = tid; idx < 32 * 288; idx += TB) {
        int nc = idx / 288;
        int k  = idx % 288;
        sw[k * 32 + nc] = __half2float(__float2half_rn(w[(nhalf * 32 + nc) * 288 + k]));
    }

    // ---- input rows y0-1..y0+4, 32 ch, padded rows of 60 (x offset by 1) ----
    const float* xb = x + (size_t)b * 32 * 56 * 56;
    for (int idx = tid; idx < SIN_FLOATS; idx += TB) {
        int c   = idx / (NROWS * ROWP);
        int rr  = idx % (NROWS * ROWP);
        int r   = rr / ROWP;
        int xs  = rr % ROWP;
        int yg  = y0 - 1 + r;
        int xg  = xs - 1;
        float v = 0.0f;
        if (yg >= 0 && yg < 56 && xg >= 0 && xg < 56)
            v = xb[(c * 56 + yg) * 56 + xg];
        sin[idx] = v;
    }
    __syncthreads();

    const int lane = tid & 31;
    const int wrp  = tid >> 5;            // 0..13
    const int np   = lane & 15;           // n-pair within half
    const int h    = lane >> 4;           // px group half 0/1
    const int grp  = wrp * 2 + h;         // 0..27
    const int row  = grp / 7;             // 0..3 (output row within quad)
    const int x0   = (grp % 7) * 8;       // output x base, 8 px per thread

    __half2 acc[8];
    #pragma unroll
    for (int p = 0; p < 8; ++p) acc[p] = __float2half2_rn(0.0f);

    const float* swt = sw + 2 * np;
    const float* ab  = sin + row * ROWP + x0;   // 16B aligned

    #pragma unroll 1
    for (int c = 0; c < 32; ++c) {
        #pragma unroll
        for (int i = 0; i < 3; ++i) {
            const float* ar = ab + (c * NROWS + i) * ROWP;
            float4 a03 = *reinterpret_cast<const float4*>(ar);
            float4 a47 = *reinterpret_cast<const float4*>(ar + 4);
            float2 a89 = *reinterpret_cast<const float2*>(ar + 8);
            float av[10] = { a03.x, a03.y, a03.z, a03.w,
                             a47.x, a47.y, a47.z, a47.w,
                             a89.x, a89.y };

            const float* wr = swt + (c * 9 + i * 3) * 32;
            float2 w0 = *reinterpret_cast<const float2*>(wr);        // j=0
            float2 w1 = *reinterpret_cast<const float2*>(wr + 32);   // j=1
            float2 w2 = *reinterpret_cast<const float2*>(wr + 64);   // j=2

            #pragma unroll
            for (int p = 0; p < 8; ++p)
                acc[p] = __hadd2(acc[p], cvt_pair(av[p] * w0.x, av[p] * w0.y));
            #pragma unroll
            for (int p = 0; p < 8; ++p)
                acc[p] = __hadd2(acc[p], cvt_pair(av[p + 1] * w1.x, av[p + 1] * w1.y));
            #pragma unroll
            for (int p = 0; p < 8; ++p)
                acc[p] = __hadd2(acc[p], cvt_pair(av[p + 2] * w2.x, av[p + 2] * w2.y));
        }
    }

    // ---- epilogue: out = fp32(fp16(acc + fp16(bias))) ----
    const int n0 = nhalf * 32 + 2 * np;
    __half2 qb = __halves2half2(__float2half_rn(bias[n0]),
                                __float2half_rn(bias[n0 + 1]));

    float o0v[8], o1v[8];
    #pragma unroll
    for (int p = 0; p < 8; ++p) {
        __half2 r = __hadd2(acc[p], qb);
        o0v[p] = __low2float(r);
        o1v[p] = __high2float(r);
    }

    const int y = y0 + row;
    size_t o0 = (((size_t)b * 64 + n0) * 56 + y) * 56 + x0;
    size_t o1 = (((size_t)b * 64 + n0 + 1) * 56 + y) * 56 + x0;
    #pragma unroll
    for (int q = 0; q < 2; ++q) {
        float4 v0 = make_float4(o0v[q*4+0], o0v[q*4+1], o0v[q*4+2], o0v[q*4+3]);
        float4 v1 = make_float4(o1v[q*4+0], o1v[q*4+1], o1v[q*4+2], o1v[q*4+3]);
        *reinterpret_cast<float4*>(out + o0 + q * 4) = v0;
        *reinterpret_cast<float4*>(out + o1 + q * 4) = v1;
    }
}

extern "C" void kernel_launch(void* const* d_in, const int* in_sizes, int n_in,
                              void* d_out, int out_size)
{
    const float* x    = (const float*)d_in[0];
    const float* w    = (const float*)d_in[1];
    const float* bias = (const float*)d_in[2];
    float* out = (float*)d_out;

    cudaFuncSetAttribute(qconv2d_kernel,
                         cudaFuncAttributeMaxDynamicSharedMemorySize,
                         SMEM_BYTES);

    dim3 grid(14, 16, 2);   // (row quad, batch, n-half)
    qconv2d_kernel<<<grid, TB, SMEM_BYTES>>>(x, w, bias, out);
}